// round 13
// baseline (speedup 1.0000x reference)
#include <cuda_runtime.h>
#include <math.h>

#define BATCH   1024
#define SEQ     200
#define HID     128
#define VOCAB   100000
#define PAD_ID      99998
#define INTEREST_ID 99999
#define NTHR    256

// scratch: final per-(b,s) attention weight (0 for masked positions)
__device__ float g_weights[BATCH * SEQ];

__device__ __forceinline__ float fast_tanh(float x) {
    float y;
    asm("tanh.approx.f32 %0, %1;" : "=f"(y) : "f"(x));
    return y;
}

// ---------------------------------------------------------------------------
// Score kernel: pure reads. scores -> max-free masked softmax -> weights.
// Runs CONCURRENTLY with the output memset (touches only hs/ids/scratch).
// ---------------------------------------------------------------------------
__global__ __launch_bounds__(NTHR, 7) void score_kernel(
    const float* __restrict__ hs,   // (B, S, H) fp32
    const int*   __restrict__ ids,  // (B, S) int32
    const float* __restrict__ w,    // (H,)
    const float* __restrict__ bp)   // (1,)
{
    const int b    = blockIdx.x;
    const int tid  = threadIdx.x;
    const int lane = tid & 31;
    const int warp = tid >> 5;

    __shared__ float s_scores[SEQ];
    __shared__ float red[8];

    // lane l owns H-elements [4l, 4l+4)
    const float4* hb  = reinterpret_cast<const float4*>(hs + (size_t)b * SEQ * HID);
    const float4  key = hb[lane];                               // hidden[b,0,:]
    const float4  wp  = reinterpret_cast<const float4*>(w)[lane];
    const float   bias = bp[0];

    // 25 s-rows per warp: 8 triples (MLP=3) + 1 tail
    #pragma unroll 1
    for (int jo = 0; jo < 24; jo += 3) {
        float4 hv[3];
        #pragma unroll
        for (int u = 0; u < 3; ++u)
            hv[u] = hb[(warp + 8 * (jo + u)) * (HID / 4) + lane];

        float p[3];
        #pragma unroll
        for (int u = 0; u < 3; ++u) {
            p[u] = fast_tanh(hv[u].x + key.x) * wp.x
                 + fast_tanh(hv[u].y + key.y) * wp.y
                 + fast_tanh(hv[u].z + key.z) * wp.z
                 + fast_tanh(hv[u].w + key.w) * wp.w;
        }
        #pragma unroll
        for (int o = 16; o; o >>= 1) {
            #pragma unroll
            for (int u = 0; u < 3; ++u)
                p[u] += __shfl_xor_sync(0xffffffffu, p[u], o);
        }
        if (lane == 0) {
            #pragma unroll
            for (int u = 0; u < 3; ++u)
                s_scores[warp + 8 * (jo + u)] = p[u] + bias;
        }
    }
    {   // tail: j = 24
        const int s = warp + 8 * 24;
        float4 hv = hb[s * (HID / 4) + lane];
        float p = fast_tanh(hv.x + key.x) * wp.x
                + fast_tanh(hv.y + key.y) * wp.y
                + fast_tanh(hv.z + key.z) * wp.z
                + fast_tanh(hv.w + key.w) * wp.w;
        #pragma unroll
        for (int o = 16; o; o >>= 1) p += __shfl_xor_sync(0xffffffffu, p, o);
        if (lane == 0) s_scores[s] = p + bias;
    }
    __syncthreads();

    // max-free masked softmax (|score| <= ~9, exp never overflows fp32)
    float e = 0.f;
    if (tid < SEQ) {
        const int id = ids[(size_t)b * SEQ + tid];
        const bool valid = (id != PAD_ID) && (id != INTEREST_ID);
        e = valid ? __expf(s_scores[tid]) : 0.f;
    }

    float ssum = e;
    #pragma unroll
    for (int o = 16; o; o >>= 1) ssum += __shfl_xor_sync(0xffffffffu, ssum, o);
    if (lane == 0) red[warp] = ssum;
    __syncthreads();
    if (warp == 0) {
        float tt = red[lane & 7];
        #pragma unroll
        for (int o = 4; o; o >>= 1) tt += __shfl_xor_sync(0xffffffffu, tt, o);
        if (lane == 0) red[0] = tt;
    }
    __syncthreads();
    const float inv_sum = 1.0f / red[0];

    if (tid < SEQ) {
        g_weights[(size_t)b * SEQ + tid] = e * inv_sum;   // 0 for masked
    }
}

// ---------------------------------------------------------------------------
// Scatter kernel: after memset AND scores complete. 204800 spread atomics.
// ---------------------------------------------------------------------------
__global__ __launch_bounds__(NTHR) void scatter_kernel(
    const int* __restrict__ ids,    // (B, S) int32
    float* __restrict__ out)        // (B, VOCAB) fp32, zeroed
{
    const int i = blockIdx.x * NTHR + threadIdx.x;   // i in [0, B*S)
    if (i >= BATCH * SEQ) return;
    const float wgt = g_weights[i];
    if (wgt != 0.f) {
        const int b  = i / SEQ;
        const int id = ids[i];
        atomicAdd(out + (size_t)b * VOCAB + id, wgt);
    }
}

extern "C" void kernel_launch(void* const* d_in, const int* in_sizes, int n_in,
                              void* d_out, int out_size) {
    const float* hs  = (const float*)d_in[0];
    const int*   ids = (const int*)d_in[1];
    const float* w   = (const float*)d_in[2];
    const float* bp  = (const float*)d_in[3];
    float*       out = (float*)d_out;

    // One-time setup (first call is the non-captured correctness run).
    static cudaStream_t s2      = nullptr;
    static cudaEvent_t  ev_fork = nullptr;
    static cudaEvent_t  ev_join = nullptr;
    if (!s2) {
        cudaStreamCreateWithFlags(&s2, cudaStreamNonBlocking);
        cudaEventCreateWithFlags(&ev_fork, cudaEventDisableTiming);
        cudaEventCreateWithFlags(&ev_join, cudaEventDisableTiming);
    }

    // Fork: memset (410 MB writes) on s2 concurrent with score kernel (reads).
    cudaEventRecord(ev_fork, 0);
    cudaStreamWaitEvent(s2, ev_fork, 0);
    cudaMemsetAsync(out, 0, (size_t)out_size * sizeof(float), s2);

    score_kernel<<<BATCH, NTHR>>>(hs, ids, w, bp);

    // Join: scatter needs both the zeroed output and the weights.
    cudaEventRecord(ev_join, s2);
    cudaStreamWaitEvent(0, ev_join, 0);
    scatter_kernel<<<(BATCH * SEQ + NTHR - 1) / NTHR, NTHR>>>(ids, out);
}

// round 14
// speedup vs baseline: 1.0902x; 1.0902x over previous
#include <cuda_runtime.h>
#include <math.h>
#include <stdint.h>

#define BATCH   1024
#define SEQ     200
#define HID     128
#define VOCAB   100000
#define PAD_ID      99998
#define INTEREST_ID 99999
#define NTHR    256

#define CHUNK_J     3                     // j-steps per chunk
#define CHUNK_ROWS  24                    // 8 warps * 3 j-steps
#define CHUNK_FLT   (CHUNK_ROWS * HID)    // 3072 floats
#define CHUNK_BYTES (CHUNK_FLT * 4)       // 12288 B
#define NCHUNKS     8                     // j = 0..23; j = 24 is the tail

__device__ __forceinline__ float fast_tanh(float x) {
    float y;
    asm("tanh.approx.f32 %0, %1;" : "=f"(y) : "f"(x));
    return y;
}

__device__ __forceinline__ void cp16(uint32_t dst_smem, const void* src) {
    asm volatile("cp.async.cg.shared.global [%0], [%1], 16;"
                 :: "r"(dst_smem), "l"(src));
}

// ---------------------------------------------------------------------------
// Fused: cp.async-staged scores -> max-free masked softmax -> scatter-add.
// One CTA per batch row, occ 7 (1036 slots >= 1024 -> single wave).
// Double-buffered 12 KB chunks: copy c+1 overlaps compute of c.
// ---------------------------------------------------------------------------
__global__ __launch_bounds__(NTHR, 7) void score_scatter_kernel(
    const float* __restrict__ hs,   // (B, S, H) fp32
    const int*   __restrict__ ids,  // (B, S) int32
    const float* __restrict__ w,    // (H,)
    const float* __restrict__ bp,   // (1,)
    float* __restrict__ out)        // (B, VOCAB) fp32, already zeroed
{
    const int b    = blockIdx.x;
    const int tid  = threadIdx.x;
    const int lane = tid & 31;
    const int warp = tid >> 5;

    __shared__ __align__(16) float buf[2][CHUNK_FLT];   // 24.0 KB
    __shared__ float s_scores[SEQ];
    __shared__ float red[8];

    const char* hrow = (const char*)(hs + (size_t)b * SEQ * HID);

    // key = hidden[b,0,:], weights: small cached LDGs
    const float4 key = reinterpret_cast<const float4*>(hrow)[lane];
    const float4 wp  = reinterpret_cast<const float4*>(w)[lane];
    const float  bias = bp[0];

    const uint32_t sbuf0 = (uint32_t)__cvta_generic_to_shared(&buf[0][0]);
    const uint32_t sbuf1 = (uint32_t)__cvta_generic_to_shared(&buf[1][0]);

    // --- prologue: stage chunk 0 ---
    {
        const char* src = hrow + (size_t)tid * 16;
        uint32_t dst = sbuf0 + tid * 16;
        #pragma unroll
        for (int k = 0; k < 3; ++k)
            cp16(dst + k * 4096, src + k * 4096);
        asm volatile("cp.async.commit_group;");
    }

    // --- main pipeline over 8 chunks (rows 0..191) ---
    #pragma unroll 1
    for (int c = 0; c < NCHUNKS; ++c) {
        const uint32_t sbuf_next = ((c + 1) & 1) ? sbuf1 : sbuf0;
        if (c + 1 < NCHUNKS) {
            const char* src = hrow + (size_t)(c + 1) * CHUNK_BYTES + (size_t)tid * 16;
            uint32_t dst = sbuf_next + tid * 16;
            #pragma unroll
            for (int k = 0; k < 3; ++k)
                cp16(dst + k * 4096, src + k * 4096);
            asm volatile("cp.async.commit_group;");
            asm volatile("cp.async.wait_group 1;");   // chunk c complete
        } else {
            asm volatile("cp.async.wait_group 0;");   // last chunk complete
        }
        __syncthreads();

        const float* cb = (c & 1) ? buf[1] : buf[0];
        // warp handles local rows warp + 8*jl, jl = 0..2 (3 independent chains)
        float4 hv[CHUNK_J];
        #pragma unroll
        for (int jl = 0; jl < CHUNK_J; ++jl)
            hv[jl] = reinterpret_cast<const float4*>(cb + (warp + 8 * jl) * HID)[lane];

        float p[CHUNK_J];
        #pragma unroll
        for (int jl = 0; jl < CHUNK_J; ++jl) {
            p[jl] = fast_tanh(hv[jl].x + key.x) * wp.x
                  + fast_tanh(hv[jl].y + key.y) * wp.y
                  + fast_tanh(hv[jl].z + key.z) * wp.z
                  + fast_tanh(hv[jl].w + key.w) * wp.w;
        }
        #pragma unroll
        for (int o = 16; o; o >>= 1) {
            #pragma unroll
            for (int jl = 0; jl < CHUNK_J; ++jl)
                p[jl] += __shfl_xor_sync(0xffffffffu, p[jl], o);
        }
        if (lane == 0) {
            #pragma unroll
            for (int jl = 0; jl < CHUNK_J; ++jl)
                s_scores[CHUNK_ROWS * c + warp + 8 * jl] = p[jl] + bias;
        }
        __syncthreads();   // all warps done reading this buffer before reuse
    }

    // --- tail: rows 192..199 (j = 24), direct LDG ---
    {
        const int s = 192 + warp;
        float4 hv = reinterpret_cast<const float4*>(hrow + (size_t)s * HID * 4)[lane];
        float p = fast_tanh(hv.x + key.x) * wp.x
                + fast_tanh(hv.y + key.y) * wp.y
                + fast_tanh(hv.z + key.z) * wp.z
                + fast_tanh(hv.w + key.w) * wp.w;
        #pragma unroll
        for (int o = 16; o; o >>= 1) p += __shfl_xor_sync(0xffffffffu, p, o);
        if (lane == 0) s_scores[s] = p + bias;
    }
    __syncthreads();

    // ---- max-free masked softmax (|score| <= ~9, exp never overflows) ----
    int   my_id = 0;
    float e     = 0.f;
    if (tid < SEQ) {
        my_id = ids[(size_t)b * SEQ + tid];
        const bool valid = (my_id != PAD_ID) && (my_id != INTEREST_ID);
        e = valid ? __expf(s_scores[tid]) : 0.f;
    }

    float ssum = e;
    #pragma unroll
    for (int o = 16; o; o >>= 1) ssum += __shfl_xor_sync(0xffffffffu, ssum, o);
    if (lane == 0) red[warp] = ssum;
    __syncthreads();
    if (warp == 0) {
        float tt = red[lane & 7];
        #pragma unroll
        for (int o = 4; o; o >>= 1) tt += __shfl_xor_sync(0xffffffffu, tt, o);
        if (lane == 0) red[0] = tt;
    }
    __syncthreads();
    const float inv_sum = 1.0f / red[0];

    // scatter into this block's private (pre-zeroed) row
    if (e != 0.f) {
        atomicAdd(out + (size_t)b * VOCAB + my_id, e * inv_sum);
    }
}

extern "C" void kernel_launch(void* const* d_in, const int* in_sizes, int n_in,
                              void* d_out, int out_size) {
    const float* hs  = (const float*)d_in[0];
    const int*   ids = (const int*)d_in[1];
    const float* w   = (const float*)d_in[2];
    const float* bp  = (const float*)d_in[3];
    float*       out = (float*)d_out;

    // Driver-tuned zero-fill of the 410 MB output (graph memset node, ~6.8 TB/s).
    cudaMemsetAsync(out, 0, (size_t)out_size * sizeof(float));

    // Staged reads + fused scatter; ordered after the memset by stream order.
    score_scatter_kernel<<<BATCH, NTHR>>>(hs, ids, w, bp, out);
}